// round 1
// baseline (speedup 1.0000x reference)
#include <cuda_runtime.h>

// Problem constants
#define PL (512*512)

// ---------------- scratch (static __device__ — no allocations) ----------------
__device__ float g_t[8][4][16][2];       // einsum result, reshaped
__device__ float g_scal[3];              // epilogue affine scalars A, B, K
__device__ float g_part[8][512][2];      // per-(b,m) partial sums of mr, mr^2
__device__ float g_stats[8][2];          // per-batch sum(mr), sum(mr^2)
__device__ float g_mi[8][2][16][512];    // planar [b][re/im][r][m]
__device__ float g_mj[8][2][16][512];
__device__ float g_mod[8][2][PL];        // mod, planar [b][re/im][m*512+n]
__device__ float g_wd0[8][2][PL];        // wb*(1+mod_norm), planar
__device__ float g_P[8][2][PL];          // GEMM-1 output, stored TRANSPOSED: [b][e][n][m']
__device__ float g_Wi[2][PL];            // de-interleaved weights_i (planar [e][m][m'])
__device__ float g_Wj[2][PL];

// ---------------- k_setup: t = einsum('bc,kcl->bkl'), epilogue scalars ----------------
__global__ void k_setup(const float* __restrict__ x, const float* __restrict__ mt,
                        const float* __restrict__ td, const float* __restrict__ rd) {
    int tid = threadIdx.x;
    for (int o = tid; o < 1024; o += 256) {
        int e = o & 1, c2 = (o >> 1) & 15, k = (o >> 5) & 3, b = o >> 7;
        float s = 0.f;
        #pragma unroll
        for (int c = 0; c < 16; ++c)
            s += x[b * 16 + c] * mt[(k * 16 + c) * 32 + c2 * 2 + e];
        g_t[b][k][c2][e] = s;
    }
    if (tid == 0) {
        float A = 0.f, Bv = 0.f, K = 0.f;
        for (int c = 0; c < 16; ++c) {
            float rr = rd[2 * c], ri = rd[2 * c + 1];
            float tr = td[2 * c], ti = td[2 * c + 1];
            A += ri; Bv -= rr; K += ti * ri - tr * rr;
        }
        g_scal[0] = A; g_scal[1] = Bv; g_scal[2] = K;
    }
}

// ---------------- k_mimj: per-(b,r,m) reduce over C with rot / inversion-divide ----------------
__global__ void k_mimj(const float* __restrict__ mod_i, const float* __restrict__ mod_j,
                       const float* __restrict__ inv) {
    int b = blockIdx.x >> 4, r = blockIdx.x & 15, m = threadIdx.x;  // 512 threads
    __shared__ float st[16][8];   // st[c][k*2+e] = t[b][k][c][e]
    __shared__ float siv[16][2];
    if (m < 128) st[m >> 3][m & 7] = g_t[b][(m & 7) >> 1][m >> 3][m & 1];
    if (m < 32)  siv[m >> 1][m & 1] = inv[m];
    __syncthreads();

    float sir = 0.f, sii = 0.f, sjr = 0.f, sji = 0.f;
    #pragma unroll 4
    for (int c = 0; c < 16; ++c) {
        float t0r = st[c][0], t0i = st[c][1], t1r = st[c][2], t1i = st[c][3];
        float t2r = st[c][4], t2i = st[c][5], t3r = st[c][6], t3i = st[c][7];
        float ivr = siv[c][0], ivi = siv[c][1];
        // mi path: rot(rot(mod_i + t0, t1), inv)
        float2 vi = ((const float2*)mod_i)[(c * 16 + r) * 512 + m];
        float ar = vi.x + t0r, ai = vi.y + t0i;
        float r1 = ai * t1i - ar * t1r;
        float i1 = ar * t1i + ai * t1r;
        sir += i1 * ivi - r1 * ivr;
        sii += r1 * ivi + i1 * ivr;
        // mj path: rot(mod_j + t2, t3), then inversion-divide
        float2 vj = ((const float2*)mod_j)[(c * 16 + r) * 512 + m];
        float br2 = vj.x + t2r, bi2 = vj.y + t2i;
        float r2 = bi2 * t3i - br2 * t3r;
        float i2 = br2 * t3i + bi2 * t3r;
        float idn = 1.f / (r2 * r2 + i2 * i2);
        sjr += (ivr * r2 + ivi * i2) * idn;
        sji += (ivr * i2 - ivi * r2) * idn;
    }
    g_mi[b][0][r][m] = sir; g_mi[b][1][r][m] = sii;
    g_mj[b][0][r][m] = sjr; g_mj[b][1][r][m] = sji;
}

// ---------------- k_mod: mod = mi^T @ mj (complex, K=16) + per-(b,m) stat partials ----------------
__global__ void k_mod() {
    int b = blockIdx.x >> 9, m = blockIdx.x & 511;
    int tid = threadIdx.x;  // 128
    __shared__ float smi[2][16];
    if (tid < 32) smi[tid >> 4][tid & 15] = g_mi[b][tid >> 4][tid & 15][m];
    __syncthreads();
    float s1 = 0.f, s2 = 0.f;
    #pragma unroll
    for (int q = 0; q < 4; ++q) {
        int n = tid + q * 128;
        float cr = 0.f, ci = 0.f;
        #pragma unroll
        for (int r = 0; r < 16; ++r) {
            float air = smi[0][r], aii = smi[1][r];
            float bjr = g_mj[b][0][r][n], bji = g_mj[b][1][r][n];
            cr += air * bjr - aii * bji;
            ci += air * bji + aii * bjr;
        }
        g_mod[b][0][m * 512 + n] = cr;
        g_mod[b][1][m * 512 + n] = ci;
        s1 += cr; s2 += cr * cr;
    }
    __shared__ float rs1[128], rs2[128];
    rs1[tid] = s1; rs2[tid] = s2; __syncthreads();
    for (int off = 64; off; off >>= 1) {
        if (tid < off) { rs1[tid] += rs1[tid + off]; rs2[tid] += rs2[tid + off]; }
        __syncthreads();
    }
    if (tid == 0) { g_part[b][m][0] = rs1[0]; g_part[b][m][1] = rs2[0]; }
}

// ---------------- k_stats: deterministic final reduction ----------------
__global__ void k_stats() {
    int b = blockIdx.x, t = threadIdx.x;  // 256 threads
    __shared__ float r1[256], r2[256];
    r1[t] = g_part[b][t][0] + g_part[b][t + 256][0];
    r2[t] = g_part[b][t][1] + g_part[b][t + 256][1];
    __syncthreads();
    for (int off = 128; off; off >>= 1) {
        if (t < off) { r1[t] += r1[t + off]; r2[t] += r2[t + off]; }
        __syncthreads();
    }
    if (t == 0) { g_stats[b][0] = r1[0]; g_stats[b][1] = r2[0]; }
}

// ---------------- k_deint: de-interleave weights_i / weights_j to planar ----------------
__global__ void k_deint(const float* __restrict__ Wi, const float* __restrict__ Wj) {
    int vid = blockIdx.x * 256 + threadIdx.x;  // 131072 float4s = 262144 complex
    float4 a = ((const float4*)Wi)[vid];
    int p = vid * 2;
    g_Wi[0][p] = a.x; g_Wi[1][p] = a.y; g_Wi[0][p + 1] = a.z; g_Wi[1][p + 1] = a.w;
    float4 c = ((const float4*)Wj)[vid];
    g_Wj[0][p] = c.x; g_Wj[1][p] = c.y; g_Wj[0][p + 1] = c.z; g_Wj[1][p + 1] = c.w;
}

// ---------------- k_wd0: wd0 = wb * (1 + mod_norm), planar ----------------
__global__ void k_wd0(const float* __restrict__ wb) {
    int b = blockIdx.x >> 8;
    int seg = blockIdx.x & 255;
    int p = seg * 1024 + threadIdx.x * 4;
    float s1 = g_stats[b][0], s2 = g_stats[b][1];
    float mean = s1 * (1.f / 262144.f);
    float var = (s2 - s1 * mean) * (1.f / 262143.f);   // ddof=1
    float istd = rsqrtf(var);
    float4 mr = *(const float4*)&g_mod[b][0][p];
    float4 mi = *(const float4*)&g_mod[b][1][p];
    float4 w01 = *(const float4*)&wb[2 * p];       // (r0,i0,r1,i1)
    float4 w23 = *(const float4*)&wb[2 * p + 4];
    float4 orr = make_float4(
        w01.x * (1.f + (mr.x - mean) * istd),
        w01.z * (1.f + (mr.y - mean) * istd),
        w23.x * (1.f + (mr.z - mean) * istd),
        w23.z * (1.f + (mr.w - mean) * istd));
    float4 oii = make_float4(
        w01.y * (1.f + mi.x), w01.w * (1.f + mi.y),
        w23.y * (1.f + mi.z), w23.w * (1.f + mi.w));
    *(float4*)&g_wd0[b][0][p] = orr;
    *(float4*)&g_wd0[b][1][p] = oii;
}

// ---------------- complex GEMM: C[i,j] = sum_k A[k,i]*B[k,j] (contract-major both sides) ----
// STAGE 0: A = Wi planar, B = wd0[b]  -> writes P[b] TRANSPOSED ([n][m'])
// STAGE 1: A = P[b],     B = Wj       -> writes out[b][m'][n'] with affine epilogue
template<int STAGE>
__global__ __launch_bounds__(256, 2) void k_cgemm(float* __restrict__ gout) {
    constexpr int BI = 128, BJ = 64, BK = 16;
    const int b = blockIdx.z;
    const float* __restrict__ Ar; const float* __restrict__ Ai;
    const float* __restrict__ Br; const float* __restrict__ Bi;
    if (STAGE == 0) { Ar = g_Wi[0];   Ai = g_Wi[1];   Br = g_wd0[b][0]; Bi = g_wd0[b][1]; }
    else            { Ar = g_P[b][0]; Ai = g_P[b][1]; Br = g_Wj[0];     Bi = g_Wj[1]; }

    const int i0 = blockIdx.y * BI, j0 = blockIdx.x * BJ;
    __shared__ float Asr[BK][BI], Asi[BK][BI], Bsr[BK][BJ], Bsi[BK][BJ];
    float cr[8][4] = {}, ci[8][4] = {};
    const int tid = threadIdx.x, tx = tid & 15, ty = tid >> 4;
    const int a_kk = tid >> 5, a_ii = (tid & 31) * 4;
    const int b_kk = tid >> 4, b_jj = (tid & 15) * 4;

    for (int k0 = 0; k0 < 512; k0 += BK) {
        #pragma unroll
        for (int h = 0; h < 2; ++h) {
            int kk = a_kk + h * 8;
            *(float4*)&Asr[kk][a_ii] = *(const float4*)&Ar[(k0 + kk) * 512 + i0 + a_ii];
            *(float4*)&Asi[kk][a_ii] = *(const float4*)&Ai[(k0 + kk) * 512 + i0 + a_ii];
        }
        *(float4*)&Bsr[b_kk][b_jj] = *(const float4*)&Br[(k0 + b_kk) * 512 + j0 + b_jj];
        *(float4*)&Bsi[b_kk][b_jj] = *(const float4*)&Bi[(k0 + b_kk) * 512 + j0 + b_jj];
        __syncthreads();
        #pragma unroll 4
        for (int kk = 0; kk < BK; ++kk) {
            float ar[8], ai2[8], br[4], bi2[4];
            #pragma unroll
            for (int u = 0; u < 8; ++u) { ar[u] = Asr[kk][ty * 8 + u]; ai2[u] = Asi[kk][ty * 8 + u]; }
            #pragma unroll
            for (int v = 0; v < 4; ++v) { br[v] = Bsr[kk][tx * 4 + v]; bi2[v] = Bsi[kk][tx * 4 + v]; }
            #pragma unroll
            for (int u = 0; u < 8; ++u)
                #pragma unroll
                for (int v = 0; v < 4; ++v) {
                    cr[u][v] = fmaf(ar[u],   br[v],  cr[u][v]);
                    cr[u][v] = fmaf(-ai2[u], bi2[v], cr[u][v]);
                    ci[u][v] = fmaf(ar[u],   bi2[v], ci[u][v]);
                    ci[u][v] = fmaf(ai2[u],  br[v],  ci[u][v]);
                }
        }
        __syncthreads();
    }

    if (STAGE == 0) {
        float* Pr = g_P[b][0]; float* Pi = g_P[b][1];
        #pragma unroll
        for (int v = 0; v < 4; ++v) {
            int j = j0 + tx * 4 + v;
            int base = j * 512 + i0 + ty * 8;
            *(float4*)&Pr[base]     = make_float4(cr[0][v], cr[1][v], cr[2][v], cr[3][v]);
            *(float4*)&Pr[base + 4] = make_float4(cr[4][v], cr[5][v], cr[6][v], cr[7][v]);
            *(float4*)&Pi[base]     = make_float4(ci[0][v], ci[1][v], ci[2][v], ci[3][v]);
            *(float4*)&Pi[base + 4] = make_float4(ci[4][v], ci[5][v], ci[6][v], ci[7][v]);
        }
    } else {
        float A_ = g_scal[0], B_ = g_scal[1], K_ = g_scal[2];
        float* O = gout + b * PL;
        #pragma unroll
        for (int u = 0; u < 8; ++u) {
            int i = i0 + ty * 8 + u;
            float4 o = make_float4(
                fmaf(ci[u][0], A_, fmaf(cr[u][0], B_, K_)),
                fmaf(ci[u][1], A_, fmaf(cr[u][1], B_, K_)),
                fmaf(ci[u][2], A_, fmaf(cr[u][2], B_, K_)),
                fmaf(ci[u][3], A_, fmaf(cr[u][3], B_, K_)));
            *(float4*)&O[i * 512 + j0 + tx * 4] = o;
        }
    }
}

// ---------------- launch ----------------
extern "C" void kernel_launch(void* const* d_in, const int* in_sizes, int n_in,
                              void* d_out, int out_size) {
    (void)in_sizes; (void)n_in; (void)out_size;
    const float* x   = (const float*)d_in[0];
    const float* Wi  = (const float*)d_in[1];
    const float* Wj  = (const float*)d_in[2];
    const float* Wb  = (const float*)d_in[3];
    // d_in[4] translate_base, d_in[5] rotate_base: dead in the reference
    const float* td  = (const float*)d_in[6];
    const float* rd  = (const float*)d_in[7];
    const float* mi  = (const float*)d_in[8];
    const float* mj  = (const float*)d_in[9];
    const float* inv = (const float*)d_in[10];
    const float* mt  = (const float*)d_in[11];
    float* out = (float*)d_out;

    k_setup<<<1, 256>>>(x, mt, td, rd);
    k_mimj<<<128, 512>>>(mi, mj, inv);
    k_mod<<<4096, 128>>>();
    k_stats<<<8, 256>>>();
    k_deint<<<512, 256>>>(Wi, Wj);
    k_wd0<<<2048, 256>>>(Wb);
    dim3 grid(8, 4, 8);  // j-tiles, i-tiles, batch
    k_cgemm<0><<<grid, 256>>>(nullptr);
    k_cgemm<1><<<grid, 256>>>(out);
}